// round 15
// baseline (speedup 1.0000x reference)
#include <cuda_runtime.h>
#include <cuda_bf16.h>
#include <cstdint>

#define NODES_MAX 50176
#define NEG_SLOPE 0.01f
#define NBLK 296                           // persistent node grid: 2 CTAs/SM

// Scratch (no cudaMalloc allowed)
__device__ float g_T[NODES_MAX * 128];            // T[n] = src_h[n] @ W + b
__device__ float g_p[NODES_MAX];                  // p[n] = T[n] . Wa_z
__device__ float g_q[NODES_MAX];                  // q[n] = self_h[n] . Wa_s

__device__ __forceinline__ void ldm4(uint32_t& r0, uint32_t& r1, uint32_t& r2, uint32_t& r3,
                                     uint32_t addr) {
    asm volatile("ldmatrix.sync.aligned.m8n8.x4.shared.b16 {%0,%1,%2,%3}, [%4];"
                 : "=r"(r0), "=r"(r1), "=r"(r2), "=r"(r3) : "r"(addr));
}
__device__ __forceinline__ void mma_bf16(float* d, const uint32_t* a, const uint32_t* b) {
    asm volatile("mma.sync.aligned.m16n8k16.row.col.f32.bf16.bf16.f32 "
                 "{%0,%1,%2,%3}, {%4,%5,%6,%7}, {%8,%9}, {%0,%1,%2,%3};"
                 : "+f"(d[0]), "+f"(d[1]), "+f"(d[2]), "+f"(d[3])
                 : "r"(a[0]), "r"(a[1]), "r"(a[2]), "r"(a[3]), "r"(b[0]), "r"(b[1]));
}
__device__ __forceinline__ uint32_t smem_u32(const void* p) {
    uint32_t a;
    asm("{ .reg .u64 t; cvta.to.shared.u64 t, %1; cvt.u32.u64 %0, t; }" : "=r"(a) : "l"(p));
    return a;
}
__device__ __forceinline__ uint32_t pkbf(float a, float b) {
    __nv_bfloat162 t = __floats2bfloat162_rn(a, b);
    return *(uint32_t*)&t;
}

// ============================================================================
// K1: persistent node GEMM. Per-block inline W split (no prep kernel).
// 64 rows/tile, 256 threads (8 warps: 2M x 4N), bf16 split, 3 HMMA passes.
// q[n] fused into the tile loop (tile owns its 64 rows).
// ============================================================================
#define TSTRIDE 272
#define SM_PP   1536
#define SM_HDR  4096
#define SM_AHI  (SM_HDR)
#define SM_ALO  (SM_AHI + 64 * TSTRIDE)
#define SM_BHI  (SM_ALO + 64 * TSTRIDE)
#define SM_BLO  (SM_BHI + 128 * TSTRIDE)
#define SM_TOTAL (SM_BLO + 128 * TSTRIDE)      // 108544

__global__ __launch_bounds__(256, 2)
void node_gemm_kernel(const float* __restrict__ src_h,
                      const float* __restrict__ self_h,
                      const float* __restrict__ W,
                      const float* __restrict__ b,
                      const float* __restrict__ attn_W,
                      int n_nodes, int ntiles)
{
    extern __shared__ char smem[];
    const uint32_t sb = smem_u32(smem);
    const int tid  = threadIdx.x;
    const int wid  = tid >> 5;
    const int lane = tid & 31;

    float* sWaZ  = (float*)(smem + 0);
    float* sWaS  = (float*)(smem + 512);
    float* sB    = (float*)(smem + 1024);
    float* ppart = (float*)(smem + SM_PP);
    if (tid < 128) {
        sWaZ[tid] = attn_W[tid];
        sWaS[tid] = attn_W[128 + tid];
        sB[tid]   = b[tid];
    }

    // ---- inline W split: W[k][n] fp32 -> B tiles (row=n, col=k) hi/lo bf16 ----
    // 4096 float4 reads (k, n4..n4+3); each element -> smem row n, col k.
#pragma unroll
    for (int l = 0; l < 16; l++) {
        int i  = tid + l * 256;                // 0..4095
        int k  = i >> 5;
        int n4 = (i & 31) * 4;
        float4 v = __ldg((const float4*)&W[(size_t)k * 128 + n4]);
#pragma unroll
        for (int j = 0; j < 4; j++) {
            float x = (j == 0) ? v.x : (j == 1) ? v.y : (j == 2) ? v.z : v.w;
            __nv_bfloat16 hi = __float2bfloat16(x);
            __nv_bfloat16 lo = __float2bfloat16(x - __bfloat162float(hi));
            uint32_t off = (uint32_t)((n4 + j) * TSTRIDE + k * 2);
            *(__nv_bfloat16*)(smem + SM_BHI + off) = hi;
            *(__nv_bfloat16*)(smem + SM_BLO + off) = lo;
        }
    }
    __syncthreads();

    const int wm = (wid >> 2) * 32;
    const int wn = (wid & 3) * 32;
    const int a_row = (lane & 15);
    const int a_col = (lane >> 4) * 8;
    const int b_row = (lane & 7) + ((lane >> 4) << 3);
    const int b_col = ((lane >> 3) & 1) * 8;

    for (int tile = blockIdx.x; tile < ntiles; tile += NBLK) {
        const int row0 = tile * 64;

        // stage A: fp32 -> bf16 hi/lo
#pragma unroll
        for (int l = 0; l < 8; l++) {
            int i  = tid + l * 256;
            int r  = i >> 5;
            int c  = (i & 31) * 4;
            int row = row0 + r;
            float4 v = make_float4(0.f, 0.f, 0.f, 0.f);
            if (row < n_nodes)
                v = *(const float4*)&src_h[(size_t)row * 128 + c];
            __nv_bfloat16 h0 = __float2bfloat16(v.x), h1 = __float2bfloat16(v.y);
            __nv_bfloat16 h2 = __float2bfloat16(v.z), h3 = __float2bfloat16(v.w);
            __nv_bfloat162 p0; p0.x = h0; p0.y = h1;
            __nv_bfloat162 p1; p1.x = h2; p1.y = h3;
            *(uint2*)(smem + SM_AHI + r * TSTRIDE + c * 2) =
                make_uint2(*(uint32_t*)&p0, *(uint32_t*)&p1);
            *(uint2*)(smem + SM_ALO + r * TSTRIDE + c * 2) = make_uint2(
                pkbf(v.x - __bfloat162float(h0), v.y - __bfloat162float(h1)),
                pkbf(v.z - __bfloat162float(h2), v.w - __bfloat162float(h3)));
        }
        __syncthreads();

        // HMMA mainloop (verified fragment mapping)
        float acc[2][2][2][4];
#pragma unroll
        for (int mt = 0; mt < 2; mt++)
#pragma unroll
            for (int nt = 0; nt < 2; nt++)
#pragma unroll
                for (int s = 0; s < 2; s++)
#pragma unroll
                    for (int g = 0; g < 4; g++) acc[mt][nt][s][g] = 0.f;

#pragma unroll
        for (int ks = 0; ks < 8; ks++) {
            const int k0 = ks * 16;
            uint32_t Ah[2][4], Al[2][4], Bh[2][4], Bl[2][4];
#pragma unroll
            for (int mt = 0; mt < 2; mt++) {
                uint32_t off = (uint32_t)((wm + mt * 16 + a_row) * TSTRIDE + (k0 + a_col) * 2);
                ldm4(Ah[mt][0], Ah[mt][1], Ah[mt][2], Ah[mt][3], sb + SM_AHI + off);
                ldm4(Al[mt][0], Al[mt][1], Al[mt][2], Al[mt][3], sb + SM_ALO + off);
            }
#pragma unroll
            for (int nt = 0; nt < 2; nt++) {
                uint32_t off = (uint32_t)((wn + nt * 16 + b_row) * TSTRIDE + (k0 + b_col) * 2);
                ldm4(Bh[nt][0], Bh[nt][1], Bh[nt][2], Bh[nt][3], sb + SM_BHI + off);
                ldm4(Bl[nt][0], Bl[nt][1], Bl[nt][2], Bl[nt][3], sb + SM_BLO + off);
            }
#pragma unroll
            for (int mt = 0; mt < 2; mt++)
#pragma unroll
                for (int nt = 0; nt < 2; nt++)
#pragma unroll
                    for (int s = 0; s < 2; s++) {
                        mma_bf16(acc[mt][nt][s], Ah[mt], &Bh[nt][s * 2]);
                        mma_bf16(acc[mt][nt][s], Ah[mt], &Bl[nt][s * 2]);
                        mma_bf16(acc[mt][nt][s], Al[mt], &Bh[nt][s * 2]);
                    }
        }

        // epilogue: bias, g_T stores, p partials
        float pacc[2][2];
#pragma unroll
        for (int mt = 0; mt < 2; mt++) { pacc[mt][0] = 0.f; pacc[mt][1] = 0.f; }
#pragma unroll
        for (int mt = 0; mt < 2; mt++)
#pragma unroll
            for (int nt = 0; nt < 2; nt++)
#pragma unroll
                for (int s = 0; s < 2; s++) {
                    const int c = wn + nt * 16 + s * 8 + (lane & 3) * 2;
#pragma unroll
                    for (int h = 0; h < 2; h++) {
                        const int r = wm + mt * 16 + (lane >> 2) + h * 8;
                        float v0 = acc[mt][nt][s][h * 2 + 0] + sB[c];
                        float v1 = acc[mt][nt][s][h * 2 + 1] + sB[c + 1];
                        pacc[mt][h] += v0 * sWaZ[c] + v1 * sWaZ[c + 1];
                        if (row0 + r < n_nodes)
                            *(float2*)&g_T[(size_t)(row0 + r) * 128 + c] = make_float2(v0, v1);
                    }
                }
#pragma unroll
        for (int mt = 0; mt < 2; mt++)
#pragma unroll
            for (int h = 0; h < 2; h++) {
                float p = pacc[mt][h];
                p += __shfl_xor_sync(0xffffffffu, p, 1);
                p += __shfl_xor_sync(0xffffffffu, p, 2);
                const int r = wm + mt * 16 + (lane >> 2) + h * 8;
                if ((lane & 3) == 0) ppart[(wid & 3) * 64 + r] = p;
            }
        __syncthreads();
        if (tid < 64) {
            int row = row0 + tid;
            if (row < n_nodes)
                g_p[row] = ppart[tid] + ppart[64 + tid] + ppart[128 + tid] + ppart[192 + tid];
        }

        // ---- fused q: this tile's 64 rows, warp handles 8 rows (MLP=8) ----
        {
            const int qrow0 = row0 + wid * 8;
            float4 v[8];
#pragma unroll
            for (int j = 0; j < 8; j++) {
                int row = qrow0 + j;
                v[j] = (row < n_nodes)
                     ? __ldg((const float4*)&self_h[(size_t)row * 128] + lane)
                     : make_float4(0.f, 0.f, 0.f, 0.f);
            }
            float w0 = sWaS[lane * 4 + 0], w1 = sWaS[lane * 4 + 1];
            float w2 = sWaS[lane * 4 + 2], w3 = sWaS[lane * 4 + 3];
#pragma unroll
            for (int j = 0; j < 8; j++) {
                float s = v[j].x * w0 + v[j].y * w1 + v[j].z * w2 + v[j].w * w3;
                s += __shfl_xor_sync(0xffffffffu, s, 16);
                s += __shfl_xor_sync(0xffffffffu, s, 8);
                s += __shfl_xor_sync(0xffffffffu, s, 4);
                s += __shfl_xor_sync(0xffffffffu, s, 2);
                s += __shfl_xor_sync(0xffffffffu, s, 1);
                int row = qrow0 + j;
                if (lane == 0 && row < n_nodes) g_q[row] = s;
            }
        }
        // next iteration's stage-A is preceded by __syncthreads (above)
    }
}

// ============================================================================
// K2: edge streaming. Persistent warps, 8 edges/warp-iter (proven config),
// streaming stores; writes stay eid-sequential (key invariant).
// ============================================================================
__global__ __launch_bounds__(256)
void edge_kernel(const int* __restrict__ src_idx,
                 const int* __restrict__ dst_idx,
                 const float* __restrict__ attn_b,
                 float* __restrict__ z1,
                 float* __restrict__ e,
                 int n_edges)
{
    const int warp   = blockIdx.x * 8 + (threadIdx.x >> 5);
    const int lane   = threadIdx.x & 31;
    const int nwarps = gridDim.x * 8;
    const float ab   = __ldg(attn_b);

    for (int base = warp * 8; base < n_edges; base += nwarps * 8) {
        const int n = min(8, n_edges - base);
        int s[8];
#pragma unroll
        for (int j = 0; j < 8; j++)
            s[j] = (j < n) ? __ldg(&src_idx[base + j]) : 0;

        float4 v[8];
#pragma unroll
        for (int j = 0; j < 8; j++)
            v[j] = __ldg((const float4*)&g_T[(size_t)s[j] * 128] + lane);

#pragma unroll
        for (int j = 0; j < 8; j++)
            if (j < n)
                __stcs(((float4*)z1) + (size_t)(base + j) * 32 + lane, v[j]);

        if (lane < n) {
            int ej = base + lane;
            int ss = __ldg(&src_idx[ej]);
            int dd = __ldg(&dst_idx[ej]);
            float a = g_p[ss] + g_q[dd] + ab;
            e[ej] = (a >= 0.f) ? a : NEG_SLOPE * a;
        }
    }
}

// ============================================================================
extern "C" void kernel_launch(void* const* d_in, const int* in_sizes, int n_in,
                              void* d_out, int out_size)
{
    const float* src_h   = (const float*)d_in[0];
    const float* self_h  = (const float*)d_in[1];
    const int*   src_idx = (const int*)d_in[2];
    const int*   dst_idx = (const int*)d_in[3];
    const float* W       = (const float*)d_in[4];
    const float* b       = (const float*)d_in[5];
    const float* attn_W  = (const float*)d_in[6];
    const float* attn_b  = (const float*)d_in[7];

    int n_nodes = in_sizes[0] / 128;
    int n_edges = in_sizes[2];
    int ntiles  = (n_nodes + 63) / 64;

    float* z1 = (float*)d_out;                    // n_edges x 128
    float* e  = z1 + (size_t)n_edges * 128;       // n_edges

    cudaFuncSetAttribute(node_gemm_kernel,
                         cudaFuncAttributeMaxDynamicSharedMemorySize, SM_TOTAL);

    node_gemm_kernel<<<NBLK, 256, SM_TOTAL>>>(src_h, self_h, W, b, attn_W,
                                              n_nodes, ntiles);
    edge_kernel<<<1184, 256>>>(src_idx, dst_idx, attn_b, z1, e, n_edges);
}

// round 16
// speedup vs baseline: 1.0749x; 1.0749x over previous
#include <cuda_runtime.h>
#include <cuda_bf16.h>
#include <cstdint>

#define NODES_MAX 50176
#define NEG_SLOPE 0.01f
#define NBLK 296                           // persistent node grid: 2 CTAs/SM

// Scratch (no cudaMalloc allowed)
__device__ float g_T[NODES_MAX * 128];            // T[n] = src_h[n] @ W + b
__device__ float g_p[NODES_MAX];                  // p[n] = T[n] . Wa_z
__device__ float g_q[NODES_MAX];                  // q[n] = self_h[n] . Wa_s
__device__ __nv_bfloat16 g_Wt_hi[128 * 128];      // W^T split-high  [n][k]
__device__ __nv_bfloat16 g_Wt_lo[128 * 128];      // W^T split-low   [n][k]

__device__ __forceinline__ void ldm4(uint32_t& r0, uint32_t& r1, uint32_t& r2, uint32_t& r3,
                                     uint32_t addr) {
    asm volatile("ldmatrix.sync.aligned.m8n8.x4.shared.b16 {%0,%1,%2,%3}, [%4];"
                 : "=r"(r0), "=r"(r1), "=r"(r2), "=r"(r3) : "r"(addr));
}
__device__ __forceinline__ void mma_bf16(float* d, const uint32_t* a, const uint32_t* b) {
    asm volatile("mma.sync.aligned.m16n8k16.row.col.f32.bf16.bf16.f32 "
                 "{%0,%1,%2,%3}, {%4,%5,%6,%7}, {%8,%9}, {%0,%1,%2,%3};"
                 : "+f"(d[0]), "+f"(d[1]), "+f"(d[2]), "+f"(d[3])
                 : "r"(a[0]), "r"(a[1]), "r"(a[2]), "r"(a[3]), "r"(b[0]), "r"(b[1]));
}
__device__ __forceinline__ uint32_t smem_u32(const void* p) {
    uint32_t a;
    asm("{ .reg .u64 t; cvta.to.shared.u64 t, %1; cvt.u32.u64 %0, t; }" : "=r"(a) : "l"(p));
    return a;
}
__device__ __forceinline__ void cpasync16(uint32_t dst, const void* src) {
    asm volatile("cp.async.cg.shared.global [%0], [%1], 16;" :: "r"(dst), "l"(src) : "memory");
}
__device__ __forceinline__ uint32_t pkbf(float a, float b) {
    __nv_bfloat162 t = __floats2bfloat162_rn(a, b);
    return *(uint32_t*)&t;
}

// ============================================================================
// K0: W split (blocks [0,64)) ; q (blocks [64,...), thread-per-quarter-row,
// MLP = 8 independent float4 loads PER THREAD).
// ============================================================================
__global__ __launch_bounds__(256)
void prep_kernel(const float* __restrict__ W,
                 const float* __restrict__ self_h,
                 const float* __restrict__ attn_W,
                 int n_nodes)
{
    const int tid = threadIdx.x;
    if (blockIdx.x < 64) {
        int idx = blockIdx.x * 256 + tid;
        if (idx < 128 * 128) {
            int n = idx >> 7, k = idx & 127;
            float v = W[k * 128 + n];
            __nv_bfloat16 hi = __float2bfloat16(v);
            g_Wt_hi[idx] = hi;
            g_Wt_lo[idx] = __float2bfloat16(v - __bfloat162float(hi));
        }
    } else {
        __shared__ float sWaS[128];
        if (tid < 128) sWaS[tid] = attn_W[128 + tid];
        __syncthreads();

        const int row = (blockIdx.x - 64) * 64 + (tid >> 2);  // 64 rows/block
        const int qd  = tid & 3;                              // quarter (32 floats)

        float4 v[8];
        const float4* rowp = (const float4*)&self_h[(size_t)row * 128] + qd * 8;
        const bool ok = (row < n_nodes);
#pragma unroll
        for (int j = 0; j < 8; j++)
            v[j] = ok ? __ldg(rowp + j) : make_float4(0.f, 0.f, 0.f, 0.f);

        float s = 0.f;
#pragma unroll
        for (int j = 0; j < 8; j++) {
            const float* w = &sWaS[qd * 32 + j * 4];
            s += v[j].x * w[0] + v[j].y * w[1] + v[j].z * w[2] + v[j].w * w[3];
        }
        s += __shfl_xor_sync(0xffffffffu, s, 1);
        s += __shfl_xor_sync(0xffffffffu, s, 2);
        if (qd == 0 && ok) g_q[row] = s;
    }
}

// ============================================================================
// K1: persistent node GEMM, static tile stride. B staged once per block.
// 64 rows/tile, 256 threads (8 warps: 2M x 4N), bf16 split, 3 HMMA passes.
// ============================================================================
#define TSTRIDE 272
#define SM_PP   1536
#define SM_HDR  4096
#define SM_AHI  (SM_HDR)
#define SM_ALO  (SM_AHI + 64 * TSTRIDE)
#define SM_BHI  (SM_ALO + 64 * TSTRIDE)
#define SM_BLO  (SM_BHI + 128 * TSTRIDE)
#define SM_TOTAL (SM_BLO + 128 * TSTRIDE)      // 108544

__global__ __launch_bounds__(256, 2)
void node_gemm_kernel(const float* __restrict__ src_h,
                      const float* __restrict__ b,
                      const float* __restrict__ attn_W,
                      int n_nodes, int ntiles)
{
    extern __shared__ char smem[];
    const uint32_t sb = smem_u32(smem);
    const int tid  = threadIdx.x;
    const int wid  = tid >> 5;
    const int lane = tid & 31;

    float* sWaZ  = (float*)(smem + 0);
    float* sB    = (float*)(smem + 1024);
    float* ppart = (float*)(smem + SM_PP);
    if (tid < 128) {
        sWaZ[tid] = attn_W[tid];
        sB[tid]   = b[tid];
    }

    // stage B once per block (persists across tiles)
#pragma unroll
    for (int l = 0; l < 8; l++) {
        int i = tid + l * 256;
        int r = i >> 4, c = i & 15;
        cpasync16(sb + SM_BHI + r * TSTRIDE + c * 16, (const char*)g_Wt_hi + r * 256 + c * 16);
        cpasync16(sb + SM_BLO + r * TSTRIDE + c * 16, (const char*)g_Wt_lo + r * 256 + c * 16);
    }
    asm volatile("cp.async.commit_group;" ::: "memory");
    asm volatile("cp.async.wait_group 0;" ::: "memory");
    __syncthreads();

    const int wm = (wid >> 2) * 32;
    const int wn = (wid & 3) * 32;
    const int a_row = (lane & 15);
    const int a_col = (lane >> 4) * 8;
    const int b_row = (lane & 7) + ((lane >> 4) << 3);
    const int b_col = ((lane >> 3) & 1) * 8;

    for (int tile = blockIdx.x; tile < ntiles; tile += NBLK) {
        const int row0 = tile * 64;

        // stage A: fp32 -> bf16 hi/lo
#pragma unroll
        for (int l = 0; l < 8; l++) {
            int i  = tid + l * 256;
            int r  = i >> 5;
            int c  = (i & 31) * 4;
            int row = row0 + r;
            float4 v = make_float4(0.f, 0.f, 0.f, 0.f);
            if (row < n_nodes)
                v = *(const float4*)&src_h[(size_t)row * 128 + c];
            __nv_bfloat16 h0 = __float2bfloat16(v.x), h1 = __float2bfloat16(v.y);
            __nv_bfloat16 h2 = __float2bfloat16(v.z), h3 = __float2bfloat16(v.w);
            __nv_bfloat162 p0; p0.x = h0; p0.y = h1;
            __nv_bfloat162 p1; p1.x = h2; p1.y = h3;
            *(uint2*)(smem + SM_AHI + r * TSTRIDE + c * 2) =
                make_uint2(*(uint32_t*)&p0, *(uint32_t*)&p1);
            *(uint2*)(smem + SM_ALO + r * TSTRIDE + c * 2) = make_uint2(
                pkbf(v.x - __bfloat162float(h0), v.y - __bfloat162float(h1)),
                pkbf(v.z - __bfloat162float(h2), v.w - __bfloat162float(h3)));
        }
        __syncthreads();

        // HMMA mainloop (verified fragment mapping)
        float acc[2][2][2][4];
#pragma unroll
        for (int mt = 0; mt < 2; mt++)
#pragma unroll
            for (int nt = 0; nt < 2; nt++)
#pragma unroll
                for (int s = 0; s < 2; s++)
#pragma unroll
                    for (int g = 0; g < 4; g++) acc[mt][nt][s][g] = 0.f;

#pragma unroll
        for (int ks = 0; ks < 8; ks++) {
            const int k0 = ks * 16;
            uint32_t Ah[2][4], Al[2][4], Bh[2][4], Bl[2][4];
#pragma unroll
            for (int mt = 0; mt < 2; mt++) {
                uint32_t off = (uint32_t)((wm + mt * 16 + a_row) * TSTRIDE + (k0 + a_col) * 2);
                ldm4(Ah[mt][0], Ah[mt][1], Ah[mt][2], Ah[mt][3], sb + SM_AHI + off);
                ldm4(Al[mt][0], Al[mt][1], Al[mt][2], Al[mt][3], sb + SM_ALO + off);
            }
#pragma unroll
            for (int nt = 0; nt < 2; nt++) {
                uint32_t off = (uint32_t)((wn + nt * 16 + b_row) * TSTRIDE + (k0 + b_col) * 2);
                ldm4(Bh[nt][0], Bh[nt][1], Bh[nt][2], Bh[nt][3], sb + SM_BHI + off);
                ldm4(Bl[nt][0], Bl[nt][1], Bl[nt][2], Bl[nt][3], sb + SM_BLO + off);
            }
#pragma unroll
            for (int mt = 0; mt < 2; mt++)
#pragma unroll
                for (int nt = 0; nt < 2; nt++)
#pragma unroll
                    for (int s = 0; s < 2; s++) {
                        mma_bf16(acc[mt][nt][s], Ah[mt], &Bh[nt][s * 2]);
                        mma_bf16(acc[mt][nt][s], Ah[mt], &Bl[nt][s * 2]);
                        mma_bf16(acc[mt][nt][s], Al[mt], &Bh[nt][s * 2]);
                    }
        }

        // epilogue: bias, g_T stores, p partials
        float pacc[2][2];
#pragma unroll
        for (int mt = 0; mt < 2; mt++) { pacc[mt][0] = 0.f; pacc[mt][1] = 0.f; }
#pragma unroll
        for (int mt = 0; mt < 2; mt++)
#pragma unroll
            for (int nt = 0; nt < 2; nt++)
#pragma unroll
                for (int s = 0; s < 2; s++) {
                    const int c = wn + nt * 16 + s * 8 + (lane & 3) * 2;
#pragma unroll
                    for (int h = 0; h < 2; h++) {
                        const int r = wm + mt * 16 + (lane >> 2) + h * 8;
                        float v0 = acc[mt][nt][s][h * 2 + 0] + sB[c];
                        float v1 = acc[mt][nt][s][h * 2 + 1] + sB[c + 1];
                        pacc[mt][h] += v0 * sWaZ[c] + v1 * sWaZ[c + 1];
                        if (row0 + r < n_nodes)
                            *(float2*)&g_T[(size_t)(row0 + r) * 128 + c] = make_float2(v0, v1);
                    }
                }
#pragma unroll
        for (int mt = 0; mt < 2; mt++)
#pragma unroll
            for (int h = 0; h < 2; h++) {
                float p = pacc[mt][h];
                p += __shfl_xor_sync(0xffffffffu, p, 1);
                p += __shfl_xor_sync(0xffffffffu, p, 2);
                const int r = wm + mt * 16 + (lane >> 2) + h * 8;
                if ((lane & 3) == 0) ppart[(wid & 3) * 64 + r] = p;
            }
        __syncthreads();
        if (tid < 64) {
            int row = row0 + tid;
            if (row < n_nodes)
                g_p[row] = ppart[tid] + ppart[64 + tid] + ppart[128 + tid] + ppart[192 + tid];
        }
        // next iteration's stage-A is preceded by __syncthreads (above)
    }
}

// ============================================================================
// K2: edge streaming. Persistent warps, 8 edges/warp-iter (proven config),
// streaming stores; writes stay eid-sequential (key invariant).
// ============================================================================
__global__ __launch_bounds__(256)
void edge_kernel(const int* __restrict__ src_idx,
                 const int* __restrict__ dst_idx,
                 const float* __restrict__ attn_b,
                 float* __restrict__ z1,
                 float* __restrict__ e,
                 int n_edges)
{
    const int warp   = blockIdx.x * 8 + (threadIdx.x >> 5);
    const int lane   = threadIdx.x & 31;
    const int nwarps = gridDim.x * 8;
    const float ab   = __ldg(attn_b);

    for (int base = warp * 8; base < n_edges; base += nwarps * 8) {
        const int n = min(8, n_edges - base);
        int s[8];
#pragma unroll
        for (int j = 0; j < 8; j++)
            s[j] = (j < n) ? __ldg(&src_idx[base + j]) : 0;

        float4 v[8];
#pragma unroll
        for (int j = 0; j < 8; j++)
            v[j] = __ldg((const float4*)&g_T[(size_t)s[j] * 128] + lane);

#pragma unroll
        for (int j = 0; j < 8; j++)
            if (j < n)
                __stcs(((float4*)z1) + (size_t)(base + j) * 32 + lane, v[j]);

        if (lane < n) {
            int ej = base + lane;
            int ss = __ldg(&src_idx[ej]);
            int dd = __ldg(&dst_idx[ej]);
            float a = g_p[ss] + g_q[dd] + ab;
            e[ej] = (a >= 0.f) ? a : NEG_SLOPE * a;
        }
    }
}

// ============================================================================
extern "C" void kernel_launch(void* const* d_in, const int* in_sizes, int n_in,
                              void* d_out, int out_size)
{
    const float* src_h   = (const float*)d_in[0];
    const float* self_h  = (const float*)d_in[1];
    const int*   src_idx = (const int*)d_in[2];
    const int*   dst_idx = (const int*)d_in[3];
    const float* W       = (const float*)d_in[4];
    const float* b       = (const float*)d_in[5];
    const float* attn_W  = (const float*)d_in[6];
    const float* attn_b  = (const float*)d_in[7];

    int n_nodes = in_sizes[0] / 128;
    int n_edges = in_sizes[2];
    int ntiles  = (n_nodes + 63) / 64;

    float* z1 = (float*)d_out;                    // n_edges x 128
    float* e  = z1 + (size_t)n_edges * 128;       // n_edges

    cudaFuncSetAttribute(node_gemm_kernel,
                         cudaFuncAttributeMaxDynamicSharedMemorySize, SM_TOTAL);

    prep_kernel<<<64 + ntiles, 256>>>(W, self_h, attn_W, n_nodes);
    node_gemm_kernel<<<NBLK, 256, SM_TOTAL>>>(src_h, b, attn_W, n_nodes, ntiles);
    edge_kernel<<<1184, 256>>>(src_idx, dst_idx, attn_b, z1, e, n_edges);
}

// round 17
// speedup vs baseline: 1.1337x; 1.0547x over previous
#include <cuda_runtime.h>
#include <cuda_bf16.h>
#include <cstdint>

#define NODES_MAX 50176
#define NEG_SLOPE 0.01f
#define NBLK 296                           // persistent node grid: 2 CTAs/SM

// Scratch (no cudaMalloc allowed)
__device__ float g_T[NODES_MAX * 128];            // T[n] = src_h[n] @ W + b
__device__ float g_p[NODES_MAX];                  // p[n] = T[n] . Wa_z
__device__ float g_q[NODES_MAX];                  // q[n] = self_h[n] . Wa_s
__device__ __nv_bfloat16 g_Wt_hi[128 * 128];      // W^T split-high  [n][k]
__device__ __nv_bfloat16 g_Wt_lo[128 * 128];      // W^T split-low   [n][k]

__device__ __forceinline__ void ldm4(uint32_t& r0, uint32_t& r1, uint32_t& r2, uint32_t& r3,
                                     uint32_t addr) {
    asm volatile("ldmatrix.sync.aligned.m8n8.x4.shared.b16 {%0,%1,%2,%3}, [%4];"
                 : "=r"(r0), "=r"(r1), "=r"(r2), "=r"(r3) : "r"(addr));
}
__device__ __forceinline__ void mma_bf16(float* d, const uint32_t* a, const uint32_t* b) {
    asm volatile("mma.sync.aligned.m16n8k16.row.col.f32.bf16.bf16.f32 "
                 "{%0,%1,%2,%3}, {%4,%5,%6,%7}, {%8,%9}, {%0,%1,%2,%3};"
                 : "+f"(d[0]), "+f"(d[1]), "+f"(d[2]), "+f"(d[3])
                 : "r"(a[0]), "r"(a[1]), "r"(a[2]), "r"(a[3]), "r"(b[0]), "r"(b[1]));
}
__device__ __forceinline__ uint32_t smem_u32(const void* p) {
    uint32_t a;
    asm("{ .reg .u64 t; cvta.to.shared.u64 t, %1; cvt.u32.u64 %0, t; }" : "=r"(a) : "l"(p));
    return a;
}
__device__ __forceinline__ void cpasync16(uint32_t dst, const void* src) {
    asm volatile("cp.async.cg.shared.global [%0], [%1], 16;" :: "r"(dst), "l"(src) : "memory");
}
__device__ __forceinline__ uint32_t pkbf(float a, float b) {
    __nv_bfloat162 t = __floats2bfloat162_rn(a, b);
    return *(uint32_t*)&t;
}

// ============================================================================
// K0: W split only (tiny)
// ============================================================================
__global__ __launch_bounds__(256)
void prep_kernel(const float* __restrict__ W) {
    int idx = blockIdx.x * 256 + threadIdx.x;
    if (idx < 128 * 128) {
        int n = idx >> 7, k = idx & 127;
        float v = W[k * 128 + n];
        __nv_bfloat16 hi = __float2bfloat16(v);
        g_Wt_hi[idx] = hi;
        g_Wt_lo[idx] = __float2bfloat16(v - __bfloat162float(hi));
    }
}

// ============================================================================
// K1: persistent node GEMM, static tile stride. B staged once per block
// (cp.async), with the q prologue overlapped into the copy shadow.
// 64 rows/tile, 256 threads (8 warps: 2M x 4N), bf16 split, 3 HMMA passes.
// ============================================================================
#define QCHUNK 170                             // ceil(50176 / 296)
#define TSTRIDE 272
#define SM_PP   1536
#define SM_HDR  4096
#define SM_AHI  (SM_HDR)
#define SM_ALO  (SM_AHI + 64 * TSTRIDE)
#define SM_BHI  (SM_ALO + 64 * TSTRIDE)
#define SM_BLO  (SM_BHI + 128 * TSTRIDE)
#define SM_TOTAL (SM_BLO + 128 * TSTRIDE)      // 108544

__global__ __launch_bounds__(256, 2)
void node_gemm_kernel(const float* __restrict__ src_h,
                      const float* __restrict__ self_h,
                      const float* __restrict__ b,
                      const float* __restrict__ attn_W,
                      int n_nodes, int ntiles)
{
    extern __shared__ char smem[];
    const uint32_t sb = smem_u32(smem);
    const int tid  = threadIdx.x;
    const int wid  = tid >> 5;
    const int lane = tid & 31;

    float* sWaZ  = (float*)(smem + 0);
    float* sWaS  = (float*)(smem + 512);
    float* sB    = (float*)(smem + 1024);
    float* ppart = (float*)(smem + SM_PP);
    if (tid < 128) {
        sWaZ[tid] = attn_W[tid];
        sWaS[tid] = attn_W[128 + tid];
        sB[tid]   = b[tid];
    }

    // ---- stage B via cp.async (in flight during q prologue) ----
#pragma unroll
    for (int l = 0; l < 8; l++) {
        int i = tid + l * 256;
        int r = i >> 4, c = i & 15;
        cpasync16(sb + SM_BHI + r * TSTRIDE + c * 16, (const char*)g_Wt_hi + r * 256 + c * 16);
        cpasync16(sb + SM_BLO + r * TSTRIDE + c * 16, (const char*)g_Wt_lo + r * 256 + c * 16);
    }
    asm volatile("cp.async.commit_group;" ::: "memory");
    __syncthreads();   // sWaS visible for q prologue

    // ---- q prologue: this block's QCHUNK rows, warp-per-8-rows (R14 pattern) ----
    {
        const int qbase = blockIdx.x * QCHUNK;
        const int qend  = min(qbase + QCHUNK, n_nodes);
        for (int r0 = qbase + wid * 8; r0 < qend; r0 += 64) {
            float4 v[8];
#pragma unroll
            for (int j = 0; j < 8; j++) {
                int row = r0 + j;
                v[j] = (row < qend)
                     ? __ldg((const float4*)&self_h[(size_t)row * 128] + lane)
                     : make_float4(0.f, 0.f, 0.f, 0.f);
            }
            float w0 = sWaS[lane * 4 + 0], w1 = sWaS[lane * 4 + 1];
            float w2 = sWaS[lane * 4 + 2], w3 = sWaS[lane * 4 + 3];
#pragma unroll
            for (int j = 0; j < 8; j++) {
                float s = v[j].x * w0 + v[j].y * w1 + v[j].z * w2 + v[j].w * w3;
                s += __shfl_xor_sync(0xffffffffu, s, 16);
                s += __shfl_xor_sync(0xffffffffu, s, 8);
                s += __shfl_xor_sync(0xffffffffu, s, 4);
                s += __shfl_xor_sync(0xffffffffu, s, 2);
                s += __shfl_xor_sync(0xffffffffu, s, 1);
                int row = r0 + j;
                if (lane == 0 && row < qend) g_q[row] = s;
            }
        }
    }

    asm volatile("cp.async.wait_group 0;" ::: "memory");
    __syncthreads();

    const int wm = (wid >> 2) * 32;
    const int wn = (wid & 3) * 32;
    const int a_row = (lane & 15);
    const int a_col = (lane >> 4) * 8;
    const int b_row = (lane & 7) + ((lane >> 4) << 3);
    const int b_col = ((lane >> 3) & 1) * 8;

    for (int tile = blockIdx.x; tile < ntiles; tile += NBLK) {
        const int row0 = tile * 64;

        // stage A: fp32 -> bf16 hi/lo
#pragma unroll
        for (int l = 0; l < 8; l++) {
            int i  = tid + l * 256;
            int r  = i >> 5;
            int c  = (i & 31) * 4;
            int row = row0 + r;
            float4 v = make_float4(0.f, 0.f, 0.f, 0.f);
            if (row < n_nodes)
                v = *(const float4*)&src_h[(size_t)row * 128 + c];
            __nv_bfloat16 h0 = __float2bfloat16(v.x), h1 = __float2bfloat16(v.y);
            __nv_bfloat16 h2 = __float2bfloat16(v.z), h3 = __float2bfloat16(v.w);
            __nv_bfloat162 p0; p0.x = h0; p0.y = h1;
            __nv_bfloat162 p1; p1.x = h2; p1.y = h3;
            *(uint2*)(smem + SM_AHI + r * TSTRIDE + c * 2) =
                make_uint2(*(uint32_t*)&p0, *(uint32_t*)&p1);
            *(uint2*)(smem + SM_ALO + r * TSTRIDE + c * 2) = make_uint2(
                pkbf(v.x - __bfloat162float(h0), v.y - __bfloat162float(h1)),
                pkbf(v.z - __bfloat162float(h2), v.w - __bfloat162float(h3)));
        }
        __syncthreads();

        // HMMA mainloop (verified fragment mapping)
        float acc[2][2][2][4];
#pragma unroll
        for (int mt = 0; mt < 2; mt++)
#pragma unroll
            for (int nt = 0; nt < 2; nt++)
#pragma unroll
                for (int s = 0; s < 2; s++)
#pragma unroll
                    for (int g = 0; g < 4; g++) acc[mt][nt][s][g] = 0.f;

#pragma unroll
        for (int ks = 0; ks < 8; ks++) {
            const int k0 = ks * 16;
            uint32_t Ah[2][4], Al[2][4], Bh[2][4], Bl[2][4];
#pragma unroll
            for (int mt = 0; mt < 2; mt++) {
                uint32_t off = (uint32_t)((wm + mt * 16 + a_row) * TSTRIDE + (k0 + a_col) * 2);
                ldm4(Ah[mt][0], Ah[mt][1], Ah[mt][2], Ah[mt][3], sb + SM_AHI + off);
                ldm4(Al[mt][0], Al[mt][1], Al[mt][2], Al[mt][3], sb + SM_ALO + off);
            }
#pragma unroll
            for (int nt = 0; nt < 2; nt++) {
                uint32_t off = (uint32_t)((wn + nt * 16 + b_row) * TSTRIDE + (k0 + b_col) * 2);
                ldm4(Bh[nt][0], Bh[nt][1], Bh[nt][2], Bh[nt][3], sb + SM_BHI + off);
                ldm4(Bl[nt][0], Bl[nt][1], Bl[nt][2], Bl[nt][3], sb + SM_BLO + off);
            }
#pragma unroll
            for (int mt = 0; mt < 2; mt++)
#pragma unroll
                for (int nt = 0; nt < 2; nt++)
#pragma unroll
                    for (int s = 0; s < 2; s++) {
                        mma_bf16(acc[mt][nt][s], Ah[mt], &Bh[nt][s * 2]);
                        mma_bf16(acc[mt][nt][s], Ah[mt], &Bl[nt][s * 2]);
                        mma_bf16(acc[mt][nt][s], Al[mt], &Bh[nt][s * 2]);
                    }
        }

        // epilogue: bias, g_T stores, p partials
        float pacc[2][2];
#pragma unroll
        for (int mt = 0; mt < 2; mt++) { pacc[mt][0] = 0.f; pacc[mt][1] = 0.f; }
#pragma unroll
        for (int mt = 0; mt < 2; mt++)
#pragma unroll
            for (int nt = 0; nt < 2; nt++)
#pragma unroll
                for (int s = 0; s < 2; s++) {
                    const int c = wn + nt * 16 + s * 8 + (lane & 3) * 2;
#pragma unroll
                    for (int h = 0; h < 2; h++) {
                        const int r = wm + mt * 16 + (lane >> 2) + h * 8;
                        float v0 = acc[mt][nt][s][h * 2 + 0] + sB[c];
                        float v1 = acc[mt][nt][s][h * 2 + 1] + sB[c + 1];
                        pacc[mt][h] += v0 * sWaZ[c] + v1 * sWaZ[c + 1];
                        if (row0 + r < n_nodes)
                            *(float2*)&g_T[(size_t)(row0 + r) * 128 + c] = make_float2(v0, v1);
                    }
                }
#pragma unroll
        for (int mt = 0; mt < 2; mt++)
#pragma unroll
            for (int h = 0; h < 2; h++) {
                float p = pacc[mt][h];
                p += __shfl_xor_sync(0xffffffffu, p, 1);
                p += __shfl_xor_sync(0xffffffffu, p, 2);
                const int r = wm + mt * 16 + (lane >> 2) + h * 8;
                if ((lane & 3) == 0) ppart[(wid & 3) * 64 + r] = p;
            }
        __syncthreads();
        if (tid < 64) {
            int row = row0 + tid;
            if (row < n_nodes)
                g_p[row] = ppart[tid] + ppart[64 + tid] + ppart[128 + tid] + ppart[192 + tid];
        }
        // next iteration's stage-A is preceded by __syncthreads (above)
    }
}

// ============================================================================
// K2: edge streaming. Persistent warps, 8 edges/warp-iter (proven config),
// streaming stores; writes stay eid-sequential (key invariant).
// ============================================================================
__global__ __launch_bounds__(256)
void edge_kernel(const int* __restrict__ src_idx,
                 const int* __restrict__ dst_idx,
                 const float* __restrict__ attn_b,
                 float* __restrict__ z1,
                 float* __restrict__ e,
                 int n_edges)
{
    const int warp   = blockIdx.x * 8 + (threadIdx.x >> 5);
    const int lane   = threadIdx.x & 31;
    const int nwarps = gridDim.x * 8;
    const float ab   = __ldg(attn_b);

    for (int base = warp * 8; base < n_edges; base += nwarps * 8) {
        const int n = min(8, n_edges - base);
        int s[8];
#pragma unroll
        for (int j = 0; j < 8; j++)
            s[j] = (j < n) ? __ldg(&src_idx[base + j]) : 0;

        float4 v[8];
#pragma unroll
        for (int j = 0; j < 8; j++)
            v[j] = __ldg((const float4*)&g_T[(size_t)s[j] * 128] + lane);

#pragma unroll
        for (int j = 0; j < 8; j++)
            if (j < n)
                __stcs(((float4*)z1) + (size_t)(base + j) * 32 + lane, v[j]);

        if (lane < n) {
            int ej = base + lane;
            int ss = __ldg(&src_idx[ej]);
            int dd = __ldg(&dst_idx[ej]);
            float a = g_p[ss] + g_q[dd] + ab;
            e[ej] = (a >= 0.f) ? a : NEG_SLOPE * a;
        }
    }
}

// ============================================================================
extern "C" void kernel_launch(void* const* d_in, const int* in_sizes, int n_in,
                              void* d_out, int out_size)
{
    const float* src_h   = (const float*)d_in[0];
    const float* self_h  = (const float*)d_in[1];
    const int*   src_idx = (const int*)d_in[2];
    const int*   dst_idx = (const int*)d_in[3];
    const float* W       = (const float*)d_in[4];
    const float* b       = (const float*)d_in[5];
    const float* attn_W  = (const float*)d_in[6];
    const float* attn_b  = (const float*)d_in[7];

    int n_nodes = in_sizes[0] / 128;
    int n_edges = in_sizes[2];
    int ntiles  = (n_nodes + 63) / 64;

    float* z1 = (float*)d_out;                    // n_edges x 128
    float* e  = z1 + (size_t)n_edges * 128;       // n_edges

    cudaFuncSetAttribute(node_gemm_kernel,
                         cudaFuncAttributeMaxDynamicSharedMemorySize, SM_TOTAL);

    prep_kernel<<<64, 256>>>(W);
    node_gemm_kernel<<<NBLK, 256, SM_TOTAL>>>(src_h, self_h, b, attn_W, n_nodes, ntiles);
    edge_kernel<<<1184, 256>>>(src_idx, dst_idx, attn_b, z1, e, n_edges);
}